// round 8
// baseline (speedup 1.0000x reference)
#include <cuda_runtime.h>
#include <cstdint>
#include <math.h>

#define NTOK   16384
#define DIN    2048
#define DOUT   2048
#define RANKL  16
#define NEXP   16
#define LORA   256      // NEXP * RANKL
#define KCAT   2304     // DIN + LORA
#define RHID   64

// ---------------- scratch (static device arrays; no runtime allocation) ------------
__device__ float g_wmat[DOUT * KCAT];     // [o][k] : W | Bcat, tf32
__device__ float g_acat[LORA * DIN];      // [j][k] : A reshaped, tf32
__device__ float g_wxa[NTOK * LORA];      // coeff-weighted xa, tf32
__device__ float g_coeff[NTOK * NEXP];    // dense router coeffs
__device__ float g_rw1t[DIN * RHID];      // rw1 transposed [k][n], fp32
__device__ float g_h[NTOK * RHID];        // router hidden, fp32

// ---------------- helpers ----------------------------------------------------------
__device__ __forceinline__ float tf32r(float x) {
    uint32_t u;
    asm("cvt.rna.tf32.f32 %0, %1;" : "=r"(u) : "f"(x));
    return __uint_as_float(u);
}
__device__ __forceinline__ void cp16(float* s, const float* g) {
    uint32_t sa = (uint32_t)__cvta_generic_to_shared(s);
    asm volatile("cp.async.cg.shared.global [%0], [%1], 16;\n" :: "r"(sa), "l"(g) : "memory");
}
__device__ __forceinline__ void cp_commit() {
    asm volatile("cp.async.commit_group;\n" ::: "memory");
}
__device__ __forceinline__ void mma8(float c[4], const uint32_t a[4], const uint32_t b[2]) {
    asm volatile(
        "mma.sync.aligned.m16n8k8.row.col.f32.tf32.tf32.f32 "
        "{%0,%1,%2,%3},{%4,%5,%6,%7},{%8,%9},{%0,%1,%2,%3};\n"
        : "+f"(c[0]), "+f"(c[1]), "+f"(c[2]), "+f"(c[3])
        : "r"(a[0]), "r"(a[1]), "r"(a[2]), "r"(a[3]), "r"(b[0]), "r"(b[1]));
}

// ---------------- prep: tf32-rounded weights + transposed rw1 -----------------------
__global__ void prep_kernel(const float* __restrict__ W, const float* __restrict__ B,
                            const float* __restrict__ A, const float* __restrict__ rw1) {
    int idx = blockIdx.x * 256 + threadIdx.x;
    const int NW = DOUT * KCAT;
    const int NA = LORA * DIN;
    if (idx < NW) {
        int o = idx / KCAT, k = idx - o * KCAT;
        float v;
        if (k < DIN) v = W[o * DIN + k];
        else {
            int j = k - DIN;
            v = B[((j >> 4) * DOUT + o) * RANKL + (j & 15)];
        }
        g_wmat[idx] = tf32r(v);
    } else if (idx < NW + NA) {
        int i = idx - NW;
        g_acat[i] = tf32r(A[i]);
    } else {
        int i = idx - NW - NA;
        if (i < DIN * RHID) {
            int k = i >> 6, n = i & 63;
            g_rw1t[i] = rw1[n * DIN + k];
        }
    }
}

// ---------------- router stage 1: h = silu(x @ rw1^T + rb1), fp32 SIMT GEMM ---------
#define WS_STRIDE 68
__global__ __launch_bounds__(256)
void hgemm_router(const float* __restrict__ x, const float* __restrict__ rb1) {
    extern __shared__ float sh[];
    float* xs = sh;              // 2 stages of 128*32
    float* ws = sh + 8192;       // 2 stages of 32*WS_STRIDE

    const int t = threadIdx.x;
    const int mBase = blockIdx.x * 128;

    const int arow = t >> 3;
    const int ac4  = (t & 7) << 2;
    const int wr   = t >> 3;
    const int wc   = (t & 7) << 3;

    const int tx = t & 15;
    const int ty = t >> 4;
    const int n0 = tx * 4;
    const int m0 = ty * 8;

    float acc[8][4];
    #pragma unroll
    for (int i = 0; i < 8; i++)
        #pragma unroll
        for (int j = 0; j < 4; j++) acc[i][j] = 0.f;

    const int nTiles = DIN / 32;

    auto load = [&](int buf, int kt) {
        int k0 = kt << 5;
        float* xb = xs + buf * 4096;
        float* wb = ws + buf * 32 * WS_STRIDE;
        #pragma unroll
        for (int j = 0; j < 4; j++) {
            int row = arow + j * 32;
            cp16(xb + row * 32 + ac4, x + (size_t)(mBase + row) * DIN + k0 + ac4);
        }
        cp16(wb + wr * WS_STRIDE + wc,     g_rw1t + (size_t)(k0 + wr) * RHID + wc);
        cp16(wb + wr * WS_STRIDE + wc + 4, g_rw1t + (size_t)(k0 + wr) * RHID + wc + 4);
        cp_commit();
    };

    load(0, 0);
    for (int kt = 0; kt < nTiles; kt++) {
        int buf = kt & 1;
        if (kt + 1 < nTiles) {
            load(buf ^ 1, kt + 1);
            asm volatile("cp.async.wait_group 1;\n" ::: "memory");
        } else {
            asm volatile("cp.async.wait_group 0;\n" ::: "memory");
        }
        __syncthreads();

        const float* xb = xs + buf * 4096;
        const float* wb = ws + buf * 32 * WS_STRIDE;
        #pragma unroll
        for (int k4 = 0; k4 < 8; k4++) {
            float4 b[4];
            #pragma unroll
            for (int kk = 0; kk < 4; kk++)
                b[kk] = *reinterpret_cast<const float4*>(wb + (k4 * 4 + kk) * WS_STRIDE + n0);
            #pragma unroll
            for (int i = 0; i < 8; i++) {
                float4 av = *reinterpret_cast<const float4*>(xb + (m0 + i) * 32 + k4 * 4);
                #pragma unroll
                for (int j = 0; j < 4; j++) {
                    float bj = (j == 0 ? b[0].x : j == 1 ? b[0].y : j == 2 ? b[0].z : b[0].w);
                    float b1 = (j == 0 ? b[1].x : j == 1 ? b[1].y : j == 2 ? b[1].z : b[1].w);
                    float b2 = (j == 0 ? b[2].x : j == 1 ? b[2].y : j == 2 ? b[2].z : b[2].w);
                    float b3 = (j == 0 ? b[3].x : j == 1 ? b[3].y : j == 2 ? b[3].z : b[3].w);
                    acc[i][j] += av.x * bj + av.y * b1 + av.z * b2 + av.w * b3;
                }
            }
        }
        __syncthreads();
    }

    #pragma unroll
    for (int i = 0; i < 8; i++) {
        int tok = mBase + m0 + i;
        float4 o;
        float v0 = acc[i][0] + rb1[n0 + 0];
        float v1 = acc[i][1] + rb1[n0 + 1];
        float v2 = acc[i][2] + rb1[n0 + 2];
        float v3 = acc[i][3] + rb1[n0 + 3];
        o.x = v0 / (1.f + expf(-v0));
        o.y = v1 / (1.f + expf(-v1));
        o.z = v2 / (1.f + expf(-v2));
        o.w = v3 / (1.f + expf(-v3));
        *reinterpret_cast<float4*>(g_h + (size_t)tok * RHID + n0) = o;
    }
}

// ---------------- router stage 2: all-lane top-2 ------------------------------------
__global__ __launch_bounds__(256)
void top2_kernel(const float* __restrict__ rw2, const float* __restrict__ rb2,
                 const float* __restrict__ gates) {
    const int lane = threadIdx.x & 31;
    const int warp = threadIdx.x >> 5;
    const int tok  = blockIdx.x * 8 + warp;
    const float NEGINF = __int_as_float(0xff800000);

    const int e    = lane & 15;
    const int half = lane >> 4;

    // each pair of lanes (e, e+16) computes one expert's logit over split K
    const float4* h4 = reinterpret_cast<const float4*>(g_h + (size_t)tok * RHID + half * 32);
    const float4* w4 = reinterpret_cast<const float4*>(rw2 + (size_t)e * RHID + half * 32);
    float s = 0.f;
    #pragma unroll
    for (int i = 0; i < 8; i++) {
        float4 a = h4[i], b = w4[i];
        s += a.x * b.x + a.y * b.y + a.z * b.z + a.w * b.w;
    }
    s += __shfl_xor_sync(0xffffffffu, s, 16);
    float logit = s + rb2[e] + gates[e];

    // top-1 (strict >, ties -> lower index)
    float v = (lane < 16) ? logit : NEGINF;
    int idx = (lane < 16) ? e : 1000;
    #pragma unroll
    for (int off = 8; off; off >>= 1) {
        float ov = __shfl_down_sync(0xffffffffu, v, off);
        int   oi = __shfl_down_sync(0xffffffffu, idx, off);
        if (ov > v || (ov == v && oi < idx)) { v = ov; idx = oi; }
    }
    float v1 = __shfl_sync(0xffffffffu, v, 0);
    int   i1 = __shfl_sync(0xffffffffu, idx, 0);

    // top-2
    v = (lane < 16 && lane != i1) ? logit : NEGINF;
    idx = (lane < 16 && lane != i1) ? e : 1000;
    #pragma unroll
    for (int off = 8; off; off >>= 1) {
        float ov = __shfl_down_sync(0xffffffffu, v, off);
        int   oi = __shfl_down_sync(0xffffffffu, idx, off);
        if (ov > v || (ov == v && oi < idx)) { v = ov; idx = oi; }
    }
    float v2 = __shfl_sync(0xffffffffu, v, 0);
    int   i2 = __shfl_sync(0xffffffffu, idx, 0);

    float ex  = expf(v2 - v1);
    float inv = 1.f / (1.f + ex);
    if (lane < NEXP) {
        float c = (lane == i1) ? inv : ((lane == i2) ? ex * inv : 0.f);
        g_coeff[tok * NEXP + lane] = c;
    }
}

// ---------------- tf32 tiled GEMM: CTA 128x256, warp 64x64, 3-stage -----------------
// C[M,N] = Arow[M,K] * B[N,K]^T
// A-fragments are cvt.rna.tf32'd in-register while k0 < ksplit (the raw-x region);
// beyond ksplit the A2 source (wxa) is already tf32-rounded.
// MODE 0: epilogue wxa = tf32(coeff[row][col>>4] * acc)
// MODE 1: A split at ksplit (x then wxa); epilogue adds bias.
#define STG_FLOATS 12288   // (128+256)*32

template<int MODE>
__global__ __launch_bounds__(256, 1)
void gemm_tf32(const float* __restrict__ A1, int lda1, int ksplit,
               const float* __restrict__ A2, int lda2,
               const float* __restrict__ Bm, int ldb,
               const float* __restrict__ aux,
               float* __restrict__ C, int ldc, int K) {
    extern __shared__ float smf[];

    const int t    = threadIdx.x;
    const int lane = t & 31, warp = t >> 5;
    const int wm = warp >> 2, wn = warp & 3;     // 2 x 4 warp grid (M x N)
    const int qrow = lane >> 2, qcol = lane & 3;
    const int sw = qrow << 2;

    const int arow = t >> 3;
    const int ac4  = (t & 7) << 2;
    const int mBase = blockIdx.y * 128;
    const int nBase = blockIdx.x * 256;

    float acc[4][8][4];
    #pragma unroll
    for (int a = 0; a < 4; a++)
        #pragma unroll
        for (int b = 0; b < 8; b++)
            #pragma unroll
            for (int r = 0; r < 4; r++) acc[a][b][r] = 0.f;

    const int nTiles = K >> 5;

    auto load_tile = [&](int stage, int kt) {
        float* as = smf + stage * STG_FLOATS;
        float* bs = as + 4096;
        int k0 = kt << 5;
        #pragma unroll
        for (int j = 0; j < 4; j++) {
            int row  = arow + j * 32;
            int soff = row * 32 + (ac4 ^ ((row & 7) << 2));
            const float* srcA = (MODE == 1 && k0 >= ksplit)
                ? A2 + (size_t)(mBase + row) * lda2 + (k0 - ksplit) + ac4
                : A1 + (size_t)(mBase + row) * lda1 + k0 + ac4;
            cp16(as + soff, srcA);
        }
        #pragma unroll
        for (int j = 0; j < 8; j++) {
            int row  = arow + j * 32;
            int soff = row * 32 + (ac4 ^ ((row & 7) << 2));
            cp16(bs + soff, Bm + (size_t)row * ldb + (MODE == 1 ? (size_t)nBase * ldb : 0) + k0 + ac4);
        }
        cp_commit();
    };

    load_tile(0, 0);
    load_tile(1, 1);

    int stage = 0;
    for (int kt = 0; kt < nTiles; kt++) {
        if (kt + 2 < nTiles) {
            asm volatile("cp.async.wait_group 1;\n" ::: "memory");
        } else {
            asm volatile("cp.async.wait_group 0;\n" ::: "memory");
        }
        __syncthreads();
        if (kt + 2 < nTiles) {
            int s2 = stage + 2; if (s2 >= 3) s2 -= 3;
            load_tile(s2, kt + 2);
        }

        const bool docvt = (kt << 5) < ksplit;   // raw-x region: round A frags to tf32
        const uint32_t* as = reinterpret_cast<const uint32_t*>(smf + stage * STG_FLOATS);
        const uint32_t* bs = as + 4096;
        #pragma unroll
        for (int kk = 0; kk < 4; kk++) {
            const int c0 = kk * 8 + qcol;
            uint32_t af[4][4], bf[8][2];
            #pragma unroll
            for (int fm = 0; fm < 4; fm++) {
                int r0 = wm * 64 + fm * 16 + qrow;
                af[fm][0] = as[r0 * 32 + (c0 ^ sw)];
                af[fm][1] = as[(r0 + 8) * 32 + (c0 ^ sw)];
                af[fm][2] = as[r0 * 32 + ((c0 + 4) ^ sw)];
                af[fm][3] = as[(r0 + 8) * 32 + ((c0 + 4) ^ sw)];
            }
            if (docvt) {
                #pragma unroll
                for (int fm = 0; fm < 4; fm++)
                    #pragma unroll
                    for (int j = 0; j < 4; j++) {
                        float f = __uint_as_float(af[fm][j]);
                        asm("cvt.rna.tf32.f32 %0, %1;" : "=r"(af[fm][j]) : "f"(f));
                    }
            }
            #pragma unroll
            for (int fn = 0; fn < 8; fn++) {
                int ro = wn * 64 + fn * 8 + qrow;
                bf[fn][0] = bs[ro * 32 + (c0 ^ sw)];
                bf[fn][1] = bs[ro * 32 + ((c0 + 4) ^ sw)];
            }
            #pragma unroll
            for (int fm = 0; fm < 4; fm++)
                #pragma unroll
                for (int fn = 0; fn < 8; fn++)
                    mma8(acc[fm][fn], af[fm], bf[fn]);
        }
        __syncthreads();
        stage++; if (stage >= 3) stage = 0;
    }

    #pragma unroll
    for (int fm = 0; fm < 4; fm++) {
        int r0 = mBase + wm * 64 + fm * 16 + qrow;
        #pragma unroll
        for (int fn = 0; fn < 8; fn++) {
            int c0 = nBase + wn * 64 + fn * 8 + qcol * 2;
            if (MODE == 1) {
                float b0 = aux[c0], b1 = aux[c0 + 1];
                float2 v0 = make_float2(acc[fm][fn][0] + b0, acc[fm][fn][1] + b1);
                float2 v1 = make_float2(acc[fm][fn][2] + b0, acc[fm][fn][3] + b1);
                *reinterpret_cast<float2*>(C + (size_t)r0 * ldc + c0) = v0;
                *reinterpret_cast<float2*>(C + (size_t)(r0 + 8) * ldc + c0) = v1;
            } else {
                float s0 = aux[r0 * NEXP + (c0 >> 4)];
                float s1 = aux[(r0 + 8) * NEXP + (c0 >> 4)];
                float2 v0 = make_float2(tf32r(s0 * acc[fm][fn][0]), tf32r(s0 * acc[fm][fn][1]));
                float2 v1 = make_float2(tf32r(s1 * acc[fm][fn][2]), tf32r(s1 * acc[fm][fn][3]));
                *reinterpret_cast<float2*>(C + (size_t)r0 * ldc + c0) = v0;
                *reinterpret_cast<float2*>(C + (size_t)(r0 + 8) * ldc + c0) = v1;
            }
        }
    }
}

// ---------------- launch ------------------------------------------------------------
extern "C" void kernel_launch(void* const* d_in, const int* in_sizes, int n_in,
                              void* d_out, int out_size) {
    const float* x     = (const float*)d_in[0];
    const float* W     = (const float*)d_in[1];
    const float* bias  = (const float*)d_in[2];
    const float* rw1   = (const float*)d_in[3];
    const float* rb1   = (const float*)d_in[4];
    const float* rw2   = (const float*)d_in[5];
    const float* rb2   = (const float*)d_in[6];
    const float* A     = (const float*)d_in[7];
    const float* B     = (const float*)d_in[8];
    const float* gates = (const float*)d_in[9];
    float* out = (float*)d_out;

    const int GEMM_SMEM = 3 * STG_FLOATS * 4;                    // 147456
    const int RH_SMEM   = (2 * 4096 + 2 * 32 * WS_STRIDE) * 4;   //  50176
    cudaFuncSetAttribute(gemm_tf32<0>, cudaFuncAttributeMaxDynamicSharedMemorySize, GEMM_SMEM);
    cudaFuncSetAttribute(gemm_tf32<1>, cudaFuncAttributeMaxDynamicSharedMemorySize, GEMM_SMEM);
    cudaFuncSetAttribute(hgemm_router, cudaFuncAttributeMaxDynamicSharedMemorySize, RH_SMEM);

    void *p_wmat, *p_acat, *p_wxa, *p_coeff;
    cudaGetSymbolAddress(&p_wmat, g_wmat);
    cudaGetSymbolAddress(&p_acat, g_acat);
    cudaGetSymbolAddress(&p_wxa, g_wxa);
    cudaGetSymbolAddress(&p_coeff, g_coeff);

    // 1) prep weights (tf32 W|Bcat, Acat) + rw1 transpose
    prep_kernel<<<20992, 256>>>(W, B, A, rw1);
    // 2) router hidden: h = silu(x @ rw1^T + rb1), fp32
    hgemm_router<<<128, 256, RH_SMEM>>>(x, rb1);
    // 3) router top-2 -> g_coeff
    top2_kernel<<<2048, 256>>>(rw2, rb2, gates);
    // 4) xa = x @ Acat^T (A frags cvt'd in-register), epilogue wxa = tf32(coeff * xa)
    gemm_tf32<0><<<dim3(1, 128), 256, GEMM_SMEM>>>(
        x, DIN, DIN, nullptr, 0,
        (const float*)p_acat, DIN,
        (const float*)p_coeff, (float*)p_wxa, LORA, DIN);
    // 5) out = [x | wxa] @ [W^T ; Bcat] + bias
    gemm_tf32<1><<<dim3(8, 128), 256, GEMM_SMEM>>>(
        x, DIN, DIN,
        (const float*)p_wxa, LORA,
        (const float*)p_wmat, KCAT,
        bias, out, DOUT, KCAT);
}

// round 9
// speedup vs baseline: 1.0653x; 1.0653x over previous
#include <cuda_runtime.h>
#include <cstdint>
#include <math.h>

#define NTOK   16384
#define DIN    2048
#define DOUT   2048
#define RANKL  16
#define NEXP   16
#define LORA   256      // NEXP * RANKL
#define KCAT   2304     // DIN + LORA
#define RHID   64

// ---------------- scratch (static device arrays; no runtime allocation) ------------
__device__ float g_xt[NTOK * DIN];        // tf32-rounded x
__device__ float g_wmat[DOUT * KCAT];     // [o][k] : W | Bcat, tf32
__device__ float g_acat[LORA * DIN];      // [j][k] : A reshaped, tf32
__device__ float g_wxa[NTOK * LORA];      // coeff-weighted xa, tf32
__device__ float g_coeff[NTOK * NEXP];    // dense router coeffs
__device__ float g_rw1t[DIN * RHID];      // rw1 transposed [k][n], fp32
__device__ float g_h[NTOK * RHID];        // router hidden, fp32

// ---------------- helpers ----------------------------------------------------------
__device__ __forceinline__ float tf32r(float x) {
    uint32_t u;
    asm("cvt.rna.tf32.f32 %0, %1;" : "=r"(u) : "f"(x));
    return __uint_as_float(u);
}
__device__ __forceinline__ void cp16(float* s, const float* g) {
    uint32_t sa = (uint32_t)__cvta_generic_to_shared(s);
    asm volatile("cp.async.cg.shared.global [%0], [%1], 16;\n" :: "r"(sa), "l"(g) : "memory");
}
__device__ __forceinline__ void cp_commit() {
    asm volatile("cp.async.commit_group;\n" ::: "memory");
}
__device__ __forceinline__ void mma8(float c[4], const uint32_t a[4], const uint32_t b[2]) {
    asm volatile(
        "mma.sync.aligned.m16n8k8.row.col.f32.tf32.tf32.f32 "
        "{%0,%1,%2,%3},{%4,%5,%6,%7},{%8,%9},{%0,%1,%2,%3};\n"
        : "+f"(c[0]), "+f"(c[1]), "+f"(c[2]), "+f"(c[3])
        : "r"(a[0]), "r"(a[1]), "r"(a[2]), "r"(a[3]), "r"(b[0]), "r"(b[1]));
}

// ---------------- prep: tf32-rounded weights + transposed rw1 -----------------------
__global__ void prep_kernel(const float* __restrict__ W, const float* __restrict__ B,
                            const float* __restrict__ A, const float* __restrict__ rw1) {
    int idx = blockIdx.x * 256 + threadIdx.x;
    const int NW = DOUT * KCAT;
    const int NA = LORA * DIN;
    if (idx < NW) {
        int o = idx / KCAT, k = idx - o * KCAT;
        float v;
        if (k < DIN) v = W[o * DIN + k];
        else {
            int j = k - DIN;
            v = B[((j >> 4) * DOUT + o) * RANKL + (j & 15)];
        }
        g_wmat[idx] = tf32r(v);
    } else if (idx < NW + NA) {
        int i = idx - NW;
        g_acat[i] = tf32r(A[i]);
    } else {
        int i = idx - NW - NA;
        if (i < DIN * RHID) {
            int k = i >> 6, n = i & 63;
            g_rw1t[i] = rw1[n * DIN + k];
        }
    }
}

// ---------------- tf32-round x ------------------------------------------------------
__global__ void cvtx_kernel(const float4* __restrict__ x) {
    int i = blockIdx.x * 256 + threadIdx.x;
    float4 v = x[i];
    v.x = tf32r(v.x); v.y = tf32r(v.y); v.z = tf32r(v.z); v.w = tf32r(v.w);
    reinterpret_cast<float4*>(g_xt)[i] = v;
}

// ---------------- router stage 1: h = silu(x @ rw1^T + rb1), fp32 SIMT GEMM ---------
#define WS_STRIDE 68
__global__ __launch_bounds__(256)
void hgemm_router(const float* __restrict__ x, const float* __restrict__ rb1) {
    extern __shared__ float sh[];
    float* xs = sh;              // 2 stages of 128*32
    float* ws = sh + 8192;       // 2 stages of 32*WS_STRIDE

    const int t = threadIdx.x;
    const int mBase = blockIdx.x * 128;

    const int arow = t >> 3;
    const int ac4  = (t & 7) << 2;
    const int wr   = t >> 3;
    const int wc   = (t & 7) << 3;

    const int tx = t & 15;
    const int ty = t >> 4;
    const int n0 = tx * 4;
    const int m0 = ty * 8;

    float acc[8][4];
    #pragma unroll
    for (int i = 0; i < 8; i++)
        #pragma unroll
        for (int j = 0; j < 4; j++) acc[i][j] = 0.f;

    const int nTiles = DIN / 32;

    auto load = [&](int buf, int kt) {
        int k0 = kt << 5;
        float* xb = xs + buf * 4096;
        float* wb = ws + buf * 32 * WS_STRIDE;
        #pragma unroll
        for (int j = 0; j < 4; j++) {
            int row = arow + j * 32;
            cp16(xb + row * 32 + ac4, x + (size_t)(mBase + row) * DIN + k0 + ac4);
        }
        cp16(wb + wr * WS_STRIDE + wc,     g_rw1t + (size_t)(k0 + wr) * RHID + wc);
        cp16(wb + wr * WS_STRIDE + wc + 4, g_rw1t + (size_t)(k0 + wr) * RHID + wc + 4);
        cp_commit();
    };

    load(0, 0);
    for (int kt = 0; kt < nTiles; kt++) {
        int buf = kt & 1;
        if (kt + 1 < nTiles) {
            load(buf ^ 1, kt + 1);
            asm volatile("cp.async.wait_group 1;\n" ::: "memory");
        } else {
            asm volatile("cp.async.wait_group 0;\n" ::: "memory");
        }
        __syncthreads();

        const float* xb = xs + buf * 4096;
        const float* wb = ws + buf * 32 * WS_STRIDE;
        #pragma unroll
        for (int k4 = 0; k4 < 8; k4++) {
            float4 b[4];
            #pragma unroll
            for (int kk = 0; kk < 4; kk++)
                b[kk] = *reinterpret_cast<const float4*>(wb + (k4 * 4 + kk) * WS_STRIDE + n0);
            #pragma unroll
            for (int i = 0; i < 8; i++) {
                float4 av = *reinterpret_cast<const float4*>(xb + (m0 + i) * 32 + k4 * 4);
                #pragma unroll
                for (int j = 0; j < 4; j++) {
                    float bj = (j == 0 ? b[0].x : j == 1 ? b[0].y : j == 2 ? b[0].z : b[0].w);
                    float b1 = (j == 0 ? b[1].x : j == 1 ? b[1].y : j == 2 ? b[1].z : b[1].w);
                    float b2 = (j == 0 ? b[2].x : j == 1 ? b[2].y : j == 2 ? b[2].z : b[2].w);
                    float b3 = (j == 0 ? b[3].x : j == 1 ? b[3].y : j == 2 ? b[3].z : b[3].w);
                    acc[i][j] += av.x * bj + av.y * b1 + av.z * b2 + av.w * b3;
                }
            }
        }
        __syncthreads();
    }

    #pragma unroll
    for (int i = 0; i < 8; i++) {
        int tok = mBase + m0 + i;
        float4 o;
        float v0 = acc[i][0] + rb1[n0 + 0];
        float v1 = acc[i][1] + rb1[n0 + 1];
        float v2 = acc[i][2] + rb1[n0 + 2];
        float v3 = acc[i][3] + rb1[n0 + 3];
        o.x = v0 / (1.f + expf(-v0));
        o.y = v1 / (1.f + expf(-v1));
        o.z = v2 / (1.f + expf(-v2));
        o.w = v3 / (1.f + expf(-v3));
        *reinterpret_cast<float4*>(g_h + (size_t)tok * RHID + n0) = o;
    }
}

// ---------------- router stage 2: all-lane top-2 ------------------------------------
__global__ __launch_bounds__(256)
void top2_kernel(const float* __restrict__ rw2, const float* __restrict__ rb2,
                 const float* __restrict__ gates) {
    const int lane = threadIdx.x & 31;
    const int warp = threadIdx.x >> 5;
    const int tok  = blockIdx.x * 8 + warp;
    const float NEGINF = __int_as_float(0xff800000);

    const int e    = lane & 15;
    const int half = lane >> 4;

    // each pair of lanes (e, e+16) computes one expert's logit over split K
    const float4* h4 = reinterpret_cast<const float4*>(g_h + (size_t)tok * RHID + half * 32);
    const float4* w4 = reinterpret_cast<const float4*>(rw2 + (size_t)e * RHID + half * 32);
    float s = 0.f;
    #pragma unroll
    for (int i = 0; i < 8; i++) {
        float4 a = h4[i], b = w4[i];
        s += a.x * b.x + a.y * b.y + a.z * b.z + a.w * b.w;
    }
    s += __shfl_xor_sync(0xffffffffu, s, 16);
    float logit = s + rb2[e] + gates[e];

    // top-1 (strict >, ties -> lower index)
    float v = (lane < 16) ? logit : NEGINF;
    int idx = (lane < 16) ? e : 1000;
    #pragma unroll
    for (int off = 8; off; off >>= 1) {
        float ov = __shfl_down_sync(0xffffffffu, v, off);
        int   oi = __shfl_down_sync(0xffffffffu, idx, off);
        if (ov > v || (ov == v && oi < idx)) { v = ov; idx = oi; }
    }
    float v1 = __shfl_sync(0xffffffffu, v, 0);
    int   i1 = __shfl_sync(0xffffffffu, idx, 0);

    // top-2
    v = (lane < 16 && lane != i1) ? logit : NEGINF;
    idx = (lane < 16 && lane != i1) ? e : 1000;
    #pragma unroll
    for (int off = 8; off; off >>= 1) {
        float ov = __shfl_down_sync(0xffffffffu, v, off);
        int   oi = __shfl_down_sync(0xffffffffu, idx, off);
        if (ov > v || (ov == v && oi < idx)) { v = ov; idx = oi; }
    }
    float v2 = __shfl_sync(0xffffffffu, v, 0);
    int   i2 = __shfl_sync(0xffffffffu, idx, 0);

    float ex  = expf(v2 - v1);
    float inv = 1.f / (1.f + ex);
    if (lane < NEXP) {
        float c = (lane == i1) ? inv : ((lane == i2) ? ex * inv : 0.f);
        g_coeff[tok * NEXP + lane] = c;
    }
}

// ---------------- tf32 tiled GEMM: CTA 128x256, warp 64x64, 3-stage -----------------
// C[M,N] = Arow[M,K] * B[N,K]^T  (all operands pre-rounded to tf32)
// MODE 0: epilogue wxa = tf32(coeff[row][col>>4] * acc)
// MODE 1: A split at ksplit (x then wxa); epilogue adds bias.
#define STG_FLOATS 12288   // (128+256)*32

template<int MODE>
__global__ __launch_bounds__(256, 1)
void gemm_tf32(const float* __restrict__ A1, int lda1, int ksplit,
               const float* __restrict__ A2, int lda2,
               const float* __restrict__ Bm, int ldb,
               const float* __restrict__ aux,
               float* __restrict__ C, int ldc, int K) {
    extern __shared__ float smf[];

    const int t    = threadIdx.x;
    const int lane = t & 31, warp = t >> 5;
    const int wm = warp >> 2, wn = warp & 3;     // 2 x 4 warp grid (M x N)
    const int qrow = lane >> 2, qcol = lane & 3;
    const int sw = qrow << 2;

    const int arow = t >> 3;
    const int ac4  = (t & 7) << 2;
    const int mBase = blockIdx.y * 128;
    const int nBase = blockIdx.x * 256;

    float acc[4][8][4];
    #pragma unroll
    for (int a = 0; a < 4; a++)
        #pragma unroll
        for (int b = 0; b < 8; b++)
            #pragma unroll
            for (int r = 0; r < 4; r++) acc[a][b][r] = 0.f;

    const int nTiles = K >> 5;

    auto load_tile = [&](int stage, int kt) {
        float* as = smf + stage * STG_FLOATS;
        float* bs = as + 4096;
        int k0 = kt << 5;
        #pragma unroll
        for (int j = 0; j < 4; j++) {
            int row  = arow + j * 32;
            int soff = row * 32 + (ac4 ^ ((row & 7) << 2));
            const float* srcA = (MODE == 1 && k0 >= ksplit)
                ? A2 + (size_t)(mBase + row) * lda2 + (k0 - ksplit) + ac4
                : A1 + (size_t)(mBase + row) * lda1 + k0 + ac4;
            cp16(as + soff, srcA);
        }
        #pragma unroll
        for (int j = 0; j < 8; j++) {
            int row  = arow + j * 32;
            int soff = row * 32 + (ac4 ^ ((row & 7) << 2));
            cp16(bs + soff, Bm + (size_t)(nBase + row) * ldb + k0 + ac4);
        }
        cp_commit();
    };

    load_tile(0, 0);
    load_tile(1, 1);

    int stage = 0;
    for (int kt = 0; kt < nTiles; kt++) {
        if (kt + 2 < nTiles) {
            asm volatile("cp.async.wait_group 1;\n" ::: "memory");
        } else {
            asm volatile("cp.async.wait_group 0;\n" ::: "memory");
        }
        __syncthreads();
        if (kt + 2 < nTiles) {
            int s2 = stage + 2; if (s2 >= 3) s2 -= 3;
            load_tile(s2, kt + 2);
        }

        const uint32_t* as = reinterpret_cast<const uint32_t*>(smf + stage * STG_FLOATS);
        const uint32_t* bs = as + 4096;
        #pragma unroll
        for (int kk = 0; kk < 4; kk++) {
            const int c0 = kk * 8 + qcol;
            uint32_t af[4][4], bf[8][2];
            #pragma unroll
            for (int fm = 0; fm < 4; fm++) {
                int r0 = wm * 64 + fm * 16 + qrow;
                af[fm][0] = as[r0 * 32 + (c0 ^ sw)];
                af[fm][1] = as[(r0 + 8) * 32 + (c0 ^ sw)];
                af[fm][2] = as[r0 * 32 + ((c0 + 4) ^ sw)];
                af[fm][3] = as[(r0 + 8) * 32 + ((c0 + 4) ^ sw)];
            }
            #pragma unroll
            for (int fn = 0; fn < 8; fn++) {
                int ro = wn * 64 + fn * 8 + qrow;
                bf[fn][0] = bs[ro * 32 + (c0 ^ sw)];
                bf[fn][1] = bs[ro * 32 + ((c0 + 4) ^ sw)];
            }
            #pragma unroll
            for (int fm = 0; fm < 4; fm++)
                #pragma unroll
                for (int fn = 0; fn < 8; fn++)
                    mma8(acc[fm][fn], af[fm], bf[fn]);
        }
        __syncthreads();
        stage++; if (stage >= 3) stage = 0;
    }

    #pragma unroll
    for (int fm = 0; fm < 4; fm++) {
        int r0 = mBase + wm * 64 + fm * 16 + qrow;
        #pragma unroll
        for (int fn = 0; fn < 8; fn++) {
            int c0 = nBase + wn * 64 + fn * 8 + qcol * 2;
            if (MODE == 1) {
                float b0 = aux[c0], b1 = aux[c0 + 1];
                float2 v0 = make_float2(acc[fm][fn][0] + b0, acc[fm][fn][1] + b1);
                float2 v1 = make_float2(acc[fm][fn][2] + b0, acc[fm][fn][3] + b1);
                *reinterpret_cast<float2*>(C + (size_t)r0 * ldc + c0) = v0;
                *reinterpret_cast<float2*>(C + (size_t)(r0 + 8) * ldc + c0) = v1;
            } else {
                float s0 = aux[r0 * NEXP + (c0 >> 4)];
                float s1 = aux[(r0 + 8) * NEXP + (c0 >> 4)];
                float2 v0 = make_float2(tf32r(s0 * acc[fm][fn][0]), tf32r(s0 * acc[fm][fn][1]));
                float2 v1 = make_float2(tf32r(s1 * acc[fm][fn][2]), tf32r(s1 * acc[fm][fn][3]));
                *reinterpret_cast<float2*>(C + (size_t)r0 * ldc + c0) = v0;
                *reinterpret_cast<float2*>(C + (size_t)(r0 + 8) * ldc + c0) = v1;
            }
        }
    }
}

// ---------------- launch ------------------------------------------------------------
extern "C" void kernel_launch(void* const* d_in, const int* in_sizes, int n_in,
                              void* d_out, int out_size) {
    const float* x     = (const float*)d_in[0];
    const float* W     = (const float*)d_in[1];
    const float* bias  = (const float*)d_in[2];
    const float* rw1   = (const float*)d_in[3];
    const float* rb1   = (const float*)d_in[4];
    const float* rw2   = (const float*)d_in[5];
    const float* rb2   = (const float*)d_in[6];
    const float* A     = (const float*)d_in[7];
    const float* B     = (const float*)d_in[8];
    const float* gates = (const float*)d_in[9];
    float* out = (float*)d_out;

    const int GEMM_SMEM = 3 * STG_FLOATS * 4;                    // 147456
    const int RH_SMEM   = (2 * 4096 + 2 * 32 * WS_STRIDE) * 4;   //  50176
    cudaFuncSetAttribute(gemm_tf32<0>, cudaFuncAttributeMaxDynamicSharedMemorySize, GEMM_SMEM);
    cudaFuncSetAttribute(gemm_tf32<1>, cudaFuncAttributeMaxDynamicSharedMemorySize, GEMM_SMEM);
    cudaFuncSetAttribute(hgemm_router, cudaFuncAttributeMaxDynamicSharedMemorySize, RH_SMEM);

    void *p_xt, *p_wmat, *p_acat, *p_wxa, *p_coeff;
    cudaGetSymbolAddress(&p_xt, g_xt);
    cudaGetSymbolAddress(&p_wmat, g_wmat);
    cudaGetSymbolAddress(&p_acat, g_acat);
    cudaGetSymbolAddress(&p_wxa, g_wxa);
    cudaGetSymbolAddress(&p_coeff, g_coeff);

    // 1) prep weights (tf32 W|Bcat, Acat) + rw1 transpose
    prep_kernel<<<20992, 256>>>(W, B, A, rw1);
    // 2) tf32-round x
    cvtx_kernel<<<32768, 256>>>(reinterpret_cast<const float4*>(x));
    // 3) router hidden: h = silu(x @ rw1^T + rb1), fp32
    hgemm_router<<<128, 256, RH_SMEM>>>(x, rb1);
    // 4) router top-2 -> g_coeff
    top2_kernel<<<2048, 256>>>(rw2, rb2, gates);
    // 5) xa = x @ Acat^T, epilogue wxa = tf32(coeff * xa)   [16384 x 256, K=2048]
    gemm_tf32<0><<<dim3(1, 128), 256, GEMM_SMEM>>>(
        (const float*)p_xt, DIN, DIN, nullptr, 0,
        (const float*)p_acat, DIN,
        (const float*)p_coeff, (float*)p_wxa, LORA, DIN);
    // 6) out = [x | wxa] @ [W^T ; Bcat] + bias              [16384 x 2048, K=2304]
    gemm_tf32<1><<<dim3(8, 128), 256, GEMM_SMEM>>>(
        (const float*)p_xt, DIN, DIN,
        (const float*)p_wxa, LORA,
        (const float*)p_wmat, KCAT,
        bias, out, DOUT, KCAT);
}